// round 3
// baseline (speedup 1.0000x reference)
#include <cuda_runtime.h>

#define N_NODES 50000
#define IN_DIM  128
#define OUT_DIM 256
#define N_EDGES 800000

// Pipeline: out = relu((D^-1/2 (A+I) D^-1/2 x) W^T + b)
// Aggregation commuted before the GEMM (linearity) -> scatter moves 128 floats
// per edge instead of 256: halves atomic traffic vs reference op order.

// ---------------- scratch (no allocs allowed) ----------------
__device__ float g_deg[N_NODES];
__device__ float g_dinv[N_NODES];
__device__ float g_agg[N_NODES * IN_DIM];   // 25.6 MB aggregated features
__device__ int   g_is64;                    // edge_index dtype flag

// ---------------- dtype detection: int64 vs int32 edge_index ----------------
// If int64: the high 32-bit word of each value (< 50000) is 0 for all entries.
// For int32 random node ids, P(64 consecutive high-words == 0) ~ (2e-5)^64.
__global__ void detect_k(const int* __restrict__ ei_words, int n_pairs) {
    if (threadIdx.x == 0 && blockIdx.x == 0) {
        int n = n_pairs < 64 ? n_pairs : 64;
        int all_zero = 1;
        #pragma unroll 1
        for (int i = 0; i < n; i++) {
            if (ei_words[2 * i + 1] != 0) { all_zero = 0; break; }
        }
        g_is64 = all_zero;
    }
}

__device__ __forceinline__ void load_edge(const void* __restrict__ ei, int e,
                                          int& src, int& dst) {
    if (g_is64) {
        longlong2 v = ((const longlong2*)ei)[e];
        src = (int)v.x; dst = (int)v.y;
    } else {
        int2 v = ((const int2*)ei)[e];
        src = v.x; dst = v.y;
    }
}

// ---------------- init: zero agg, deg = 1 (self-loop) ----------------
__global__ void init_k() {
    int i = blockIdx.x * blockDim.x + threadIdx.x;
    if (i < N_NODES * IN_DIM / 4)
        ((float4*)g_agg)[i] = make_float4(0.f, 0.f, 0.f, 0.f);
    if (i < N_NODES)
        g_deg[i] = 1.0f;
}

// ---------------- degree count ----------------
__global__ __launch_bounds__(512) void deg_k(const void* __restrict__ ei) {
    int e = blockIdx.x * blockDim.x + threadIdx.x;
    if (e < N_EDGES) {
        int src, dst;
        load_edge(ei, e, src, dst);
        atomicAdd(&g_deg[dst], 1.0f);   // RED.F32 (result unused)
    }
}

// ---------------- dinv = rsqrt(deg) ----------------
__global__ void dinv_k() {
    int i = blockIdx.x * blockDim.x + threadIdx.x;
    if (i < N_NODES) g_dinv[i] = rsqrtf(g_deg[i]);
}

// ---------------- edge scatter: agg[dst] += x[src] * dinv[src]*dinv[dst] ----
// One warp per edge; lane 0 loads edge + norm, shuffle-broadcast to the warp;
// each lane handles one float4 (32 lanes * 4 = 128 dims).
__global__ __launch_bounds__(256) void scatter_k(const void* __restrict__ ei,
                                                 const float* __restrict__ x) {
    int gt = blockIdx.x * blockDim.x + threadIdx.x;
    int e    = gt >> 5;
    int lane = gt & 31;
    if (e >= N_EDGES) return;

    int src = 0, dst = 0;
    float norm = 0.f;
    if (lane == 0) {
        load_edge(ei, e, src, dst);
        norm = g_dinv[src] * g_dinv[dst];
    }
    src  = __shfl_sync(0xFFFFFFFFu, src,  0);
    dst  = __shfl_sync(0xFFFFFFFFu, dst,  0);
    norm = __shfl_sync(0xFFFFFFFFu, norm, 0);

    float4 v = ((const float4*)x)[src * 32 + lane];
    v.x *= norm; v.y *= norm; v.z *= norm; v.w *= norm;
    float* p = &g_agg[dst * IN_DIM + lane * 4];
    asm volatile("red.global.add.v4.f32 [%0], {%1, %2, %3, %4};"
                 :: "l"(p), "f"(v.x), "f"(v.y), "f"(v.z), "f"(v.w)
                 : "memory");
}

// ---------------- self-loop: agg[v] += x[v] * dinv[v]^2 (plain, post-scatter)
__global__ void selfloop_k(const float* __restrict__ x) {
    int gt = blockIdx.x * blockDim.x + threadIdx.x;
    if (gt >= N_NODES * 32) return;
    int v = gt >> 5, lane = gt & 31;
    float d = g_dinv[v];
    float s = d * d;
    float4 xv = ((const float4*)x)[v * 32 + lane];
    float4* p = (float4*)&g_agg[v * IN_DIM + lane * 4];
    float4 a = *p;
    a.x += xv.x * s; a.y += xv.y * s; a.z += xv.z * s; a.w += xv.w * s;
    *p = a;
}

// ---------------- GEMM: out = relu(agg @ W^T + b) ----------------
// M=50000, N=256, K=128. fp32 SIMT, BM=BN=128, BK=8, 256 threads, 8x8/thread.
__global__ __launch_bounds__(256) void gemm_k(const float* __restrict__ W,
                                              const float* __restrict__ bias,
                                              float* __restrict__ out) {
    __shared__ float As[8][128];
    __shared__ float Bs[8][128];
    const float* A = g_agg;
    const int bm = blockIdx.x * 128;
    const int bn = blockIdx.y * 128;
    const int tid = threadIdx.x;
    const int tx = tid & 15;       // 0..15 -> output cols tx*8..
    const int ty = tid >> 4;       // 0..15 -> output rows ty*8..
    const int lr = tid >> 1;       // 0..127 load row
    const int lc = (tid & 1) * 4;  // 0 or 4 load col (within BK)

    float acc[8][8];
    #pragma unroll
    for (int i = 0; i < 8; i++)
        #pragma unroll
        for (int j = 0; j < 8; j++) acc[i][j] = 0.f;

    for (int k0 = 0; k0 < IN_DIM; k0 += 8) {
        int arow = bm + lr;
        float4 av = make_float4(0.f, 0.f, 0.f, 0.f);
        if (arow < N_NODES)
            av = *(const float4*)&A[arow * IN_DIM + k0 + lc];
        float4 bv = *(const float4*)&W[(bn + lr) * IN_DIM + k0 + lc];
        As[lc + 0][lr] = av.x; As[lc + 1][lr] = av.y;
        As[lc + 2][lr] = av.z; As[lc + 3][lr] = av.w;
        Bs[lc + 0][lr] = bv.x; Bs[lc + 1][lr] = bv.y;
        Bs[lc + 2][lr] = bv.z; Bs[lc + 3][lr] = bv.w;
        __syncthreads();

        #pragma unroll
        for (int k = 0; k < 8; k++) {
            float4 a0 = *(const float4*)&As[k][ty * 8];
            float4 a1 = *(const float4*)&As[k][ty * 8 + 4];
            float4 b0 = *(const float4*)&Bs[k][tx * 8];
            float4 b1 = *(const float4*)&Bs[k][tx * 8 + 4];
            float a[8] = {a0.x, a0.y, a0.z, a0.w, a1.x, a1.y, a1.z, a1.w};
            float b[8] = {b0.x, b0.y, b0.z, b0.w, b1.x, b1.y, b1.z, b1.w};
            #pragma unroll
            for (int i = 0; i < 8; i++)
                #pragma unroll
                for (int j = 0; j < 8; j++)
                    acc[i][j] += a[i] * b[j];
        }
        __syncthreads();
    }

    #pragma unroll
    for (int i = 0; i < 8; i++) {
        int row = bm + ty * 8 + i;
        if (row >= N_NODES) continue;
        #pragma unroll
        for (int jj = 0; jj < 2; jj++) {
            int col = bn + tx * 8 + jj * 4;
            float4 r;
            r.x = fmaxf(acc[i][jj * 4 + 0] + bias[col + 0], 0.f);
            r.y = fmaxf(acc[i][jj * 4 + 1] + bias[col + 1], 0.f);
            r.z = fmaxf(acc[i][jj * 4 + 2] + bias[col + 2], 0.f);
            r.w = fmaxf(acc[i][jj * 4 + 3] + bias[col + 3], 0.f);
            *(float4*)&out[row * OUT_DIM + col] = r;
        }
    }
}

// ---------------- launch ----------------
extern "C" void kernel_launch(void* const* d_in, const int* in_sizes, int n_in,
                              void* d_out, int out_size) {
    const float* x  = (const float*)d_in[0];
    const void*  ei = d_in[1];
    const float* W  = (const float*)d_in[2];
    const float* b  = (const float*)d_in[3];
    float* out = (float*)d_out;

    detect_k<<<1, 32>>>((const int*)ei, N_EDGES);
    init_k<<<(N_NODES * IN_DIM / 4 + 255) / 256, 256>>>();
    deg_k<<<(N_EDGES + 511) / 512, 512>>>(ei);
    dinv_k<<<(N_NODES + 255) / 256, 256>>>();
    scatter_k<<<(N_EDGES * 32 + 255) / 256, 256>>>(ei, x);
    selfloop_k<<<(N_NODES * 32 + 255) / 256, 256>>>(x);
    dim3 grid((N_NODES + 127) / 128, OUT_DIM / 128);
    gemm_k<<<grid, 256>>>(W, b, out);
}

// round 8
// speedup vs baseline: 1.5145x; 1.5145x over previous
#include <cuda_runtime.h>
#include <cstdint>

#define N_NODES 50000
#define IN_DIM  128
#define OUT_DIM 256
#define N_EDGES 800000

// Pipeline: out = relu((D^-1/2 (A+I) D^-1/2 x) W^T + b)
// Aggregation commuted before the GEMM; GEMM on tf32 tensor cores with the
// self-loop term fused into the A-tile load. Edge records (src,dst,norm)
// precomputed so the scatter hot loop is pure gather+RED.

// ---------------- scratch (no allocs allowed) ----------------
__device__ float g_deg[N_NODES];
__device__ float g_dinv[N_NODES];
__device__ float g_agg[N_NODES * IN_DIM];   // 25.6 MB aggregated features
__device__ int4  g_edges[N_EDGES];          // 12.8 MB {src, dst, norm, pad}
__device__ int   g_is64;                    // edge_index dtype flag

// ---------------- dtype detection: int64 vs int32 edge_index ----------------
__global__ void detect_k(const int* __restrict__ ei_words, int n_pairs) {
    if (threadIdx.x == 0 && blockIdx.x == 0) {
        int n = n_pairs < 64 ? n_pairs : 64;
        int all_zero = 1;
        #pragma unroll 1
        for (int i = 0; i < n; i++) {
            if (ei_words[2 * i + 1] != 0) { all_zero = 0; break; }
        }
        g_is64 = all_zero;
    }
}

__device__ __forceinline__ void load_edge(const void* __restrict__ ei, int e,
                                          int& src, int& dst) {
    if (g_is64) {
        longlong2 v = ((const longlong2*)ei)[e];
        src = (int)v.x; dst = (int)v.y;
    } else {
        int2 v = ((const int2*)ei)[e];
        src = v.x; dst = v.y;
    }
}

// ---------------- init: zero agg, deg = 1 (self-loop) ----------------
__global__ void init_k() {
    int i = blockIdx.x * blockDim.x + threadIdx.x;
    if (i < N_NODES * IN_DIM / 4)
        ((float4*)g_agg)[i] = make_float4(0.f, 0.f, 0.f, 0.f);
    if (i < N_NODES)
        g_deg[i] = 1.0f;
}

// ---------------- degree count ----------------
__global__ __launch_bounds__(512) void deg_k(const void* __restrict__ ei) {
    int e = blockIdx.x * blockDim.x + threadIdx.x;
    if (e < N_EDGES) {
        int src, dst;
        load_edge(ei, e, src, dst);
        atomicAdd(&g_deg[dst], 1.0f);   // RED.F32 (result unused)
    }
}

// ---------------- dinv = rsqrt(deg) ----------------
__global__ void dinv_k() {
    int i = blockIdx.x * blockDim.x + threadIdx.x;
    if (i < N_NODES) g_dinv[i] = rsqrtf(g_deg[i]);
}

// ---------------- edge precompute: {src, dst, dinv[src]*dinv[dst]} ----------
__global__ __launch_bounds__(512) void prep_k(const void* __restrict__ ei) {
    int e = blockIdx.x * blockDim.x + threadIdx.x;
    if (e < N_EDGES) {
        int src, dst;
        load_edge(ei, e, src, dst);
        float norm = g_dinv[src] * g_dinv[dst];
        g_edges[e] = make_int4(src, dst, __float_as_int(norm), 0);
    }
}

// ---------------- edge scatter: agg[dst] += x[src] * norm ------------------
// One warp per edge; all 32 lanes load the same 16B edge record (L1 broadcast,
// no conflicts, no shuffles); each lane handles one float4 (32*4 = 128 dims).
__global__ __launch_bounds__(256) void scatter_k(const float* __restrict__ x) {
    int gt = blockIdx.x * blockDim.x + threadIdx.x;
    int e    = gt >> 5;
    int lane = gt & 31;
    if (e >= N_EDGES) return;

    int4 ed = g_edges[e];
    float norm = __int_as_float(ed.z);

    float4 v = ((const float4*)x)[ed.x * 32 + lane];
    v.x *= norm; v.y *= norm; v.z *= norm; v.w *= norm;
    float* p = &g_agg[ed.y * IN_DIM + lane * 4];
    asm volatile("red.global.add.v4.f32 [%0], {%1, %2, %3, %4};"
                 :: "l"(p), "f"(v.x), "f"(v.y), "f"(v.z), "f"(v.w)
                 : "memory");
}

// ---------------- tf32 helpers ----------------
__device__ __forceinline__ uint32_t f2tf32(float f) {
    uint32_t r;
    asm("cvt.rna.tf32.f32 %0, %1;" : "=r"(r) : "f"(f));
    return r;
}

// ---------------- GEMM: out = relu((agg + x*dinv^2) @ W^T + b) --------------
// M=50000, N=256, K=128. mma.sync m16n8k8 tf32. BM=128, BN=128, BK=32,
// 256 threads = 8 warps (2 x 4), warp tile 64x32. Self-loop fused in A load.
#define BK 32
#define LDS_PITCH 36   // BK + 4 pad, conflict-free for fragment loads

__global__ __launch_bounds__(256) void gemm_k(const float* __restrict__ x,
                                              const float* __restrict__ W,
                                              const float* __restrict__ bias,
                                              float* __restrict__ out) {
    __shared__ uint32_t As[128 * LDS_PITCH];
    __shared__ uint32_t Bs[128 * LDS_PITCH];

    const int t    = threadIdx.x;
    const int lane = t & 31;
    const int wid  = t >> 5;
    const int wm   = wid & 1;   // warp row (0..1) -> 64 M-rows
    const int wn   = wid >> 1;  // warp col (0..3) -> 32 N-cols
    const int bm   = blockIdx.x * 128;
    const int bn   = blockIdx.y * 128;

    const int qrow = lane >> 2;        // 0..7
    const int qcol = lane & 3;         // 0..3

    float acc[4][4][4];
    #pragma unroll
    for (int i = 0; i < 4; i++)
        #pragma unroll
        for (int j = 0; j < 4; j++)
            #pragma unroll
            for (int r = 0; r < 4; r++) acc[i][j][r] = 0.f;

    for (int k0 = 0; k0 < IN_DIM; k0 += BK) {
        // ---- load A tile (fused self-loop) and B tile ----
        #pragma unroll
        for (int i = 0; i < 4; i++) {
            int idx = t + i * 256;      // 0..1023
            int row = idx >> 3;         // 0..127
            int c4  = (idx & 7) * 4;    // 0,4,...,28
            int grow = bm + row;
            float4 av = make_float4(0.f, 0.f, 0.f, 0.f);
            if (grow < N_NODES) {
                av = *(const float4*)&g_agg[grow * IN_DIM + k0 + c4];
                float d = g_dinv[grow];
                float s = d * d;
                float4 xv = *(const float4*)&x[grow * IN_DIM + k0 + c4];
                av.x += xv.x * s; av.y += xv.y * s;
                av.z += xv.z * s; av.w += xv.w * s;
            }
            uint32_t* ap = &As[row * LDS_PITCH + c4];
            ap[0] = f2tf32(av.x); ap[1] = f2tf32(av.y);
            ap[2] = f2tf32(av.z); ap[3] = f2tf32(av.w);

            float4 bv = *(const float4*)&W[(bn + row) * IN_DIM + k0 + c4];
            uint32_t* bp = &Bs[row * LDS_PITCH + c4];
            bp[0] = f2tf32(bv.x); bp[1] = f2tf32(bv.y);
            bp[2] = f2tf32(bv.z); bp[3] = f2tf32(bv.w);
        }
        __syncthreads();

        // ---- compute: 4 k8-steps ----
        #pragma unroll
        for (int kk = 0; kk < BK; kk += 8) {
            uint32_t afrag[4][4];
            #pragma unroll
            for (int mt = 0; mt < 4; mt++) {
                int m0 = wm * 64 + mt * 16;
                const uint32_t* base = &As[kk + qcol];
                afrag[mt][0] = base[(m0 + qrow)     * LDS_PITCH];
                afrag[mt][1] = base[(m0 + 8 + qrow) * LDS_PITCH];
                afrag[mt][2] = base[(m0 + qrow)     * LDS_PITCH + 4];
                afrag[mt][3] = base[(m0 + 8 + qrow) * LDS_PITCH + 4];
            }
            uint32_t bfrag[4][2];
            #pragma unroll
            for (int nt = 0; nt < 4; nt++) {
                int n0 = wn * 32 + nt * 8;
                const uint32_t* base = &Bs[(n0 + qrow) * LDS_PITCH + kk + qcol];
                bfrag[nt][0] = base[0];
                bfrag[nt][1] = base[4];
            }
            #pragma unroll
            for (int mt = 0; mt < 4; mt++)
                #pragma unroll
                for (int nt = 0; nt < 4; nt++) {
                    asm volatile(
                        "mma.sync.aligned.m16n8k8.row.col.f32.tf32.tf32.f32 "
                        "{%0,%1,%2,%3}, {%4,%5,%6,%7}, {%8,%9}, {%0,%1,%2,%3};"
                        : "+f"(acc[mt][nt][0]), "+f"(acc[mt][nt][1]),
                          "+f"(acc[mt][nt][2]), "+f"(acc[mt][nt][3])
                        : "r"(afrag[mt][0]), "r"(afrag[mt][1]),
                          "r"(afrag[mt][2]), "r"(afrag[mt][3]),
                          "r"(bfrag[nt][0]), "r"(bfrag[nt][1]));
                }
        }
        __syncthreads();
    }

    // ---- epilogue: bias + relu ----
    #pragma unroll
    for (int mt = 0; mt < 4; mt++) {
        #pragma unroll
        for (int nt = 0; nt < 4; nt++) {
            int row0 = bm + wm * 64 + mt * 16 + qrow;
            int col  = bn + wn * 32 + nt * 8 + qcol * 2;
            float b0 = bias[col], b1 = bias[col + 1];
            if (row0 < N_NODES) {
                float2 r;
                r.x = fmaxf(acc[mt][nt][0] + b0, 0.f);
                r.y = fmaxf(acc[mt][nt][1] + b1, 0.f);
                *(float2*)&out[row0 * OUT_DIM + col] = r;
            }
            int row1 = row0 + 8;
            if (row1 < N_NODES) {
                float2 r;
                r.x = fmaxf(acc[mt][nt][2] + b0, 0.f);
                r.y = fmaxf(acc[mt][nt][3] + b1, 0.f);
                *(float2*)&out[row1 * OUT_DIM + col] = r;
            }
        }
    }
}

// ---------------- launch ----------------
extern "C" void kernel_launch(void* const* d_in, const int* in_sizes, int n_in,
                              void* d_out, int out_size) {
    const float* x  = (const float*)d_in[0];
    const void*  ei = d_in[1];
    const float* W  = (const float*)d_in[2];
    const float* b  = (const float*)d_in[3];
    float* out = (float*)d_out;

    detect_k<<<1, 32>>>((const int*)ei, N_EDGES);
    init_k<<<(N_NODES * IN_DIM / 4 + 255) / 256, 256>>>();
    deg_k<<<(N_EDGES + 511) / 512, 512>>>(ei);
    dinv_k<<<(N_NODES + 255) / 256, 256>>>();
    prep_k<<<(N_EDGES + 511) / 512, 512>>>(ei);
    scatter_k<<<(N_EDGES * 32 + 255) / 256, 256>>>(x);
    dim3 grid((N_NODES + 127) / 128, OUT_DIM / 128);
    gemm_k<<<grid, 256>>>(x, W, b, out);
}

// round 13
// speedup vs baseline: 1.9997x; 1.3204x over previous
#include <cuda_runtime.h>
#include <cstdint>

#define N_NODES 50000
#define IN_DIM  128
#define OUT_DIM 256
#define N_EDGES 800000

#define SCAN_B   512                      // nodes per scan block
#define N_SCANB  ((N_NODES + SCAN_B - 1) / SCAN_B)   // 98

// ---------------- scratch (no allocs allowed) ----------------
__device__ int   g_cnt[N_NODES];          // in-degree (edges only)
__device__ int   g_off[N_NODES];          // CSR offsets (exclusive scan)
__device__ int   g_cursor[N_NODES];       // fill cursors
__device__ float g_dinv[N_NODES];
__device__ int   g_bsum[N_SCANB];
__device__ int   g_bscan[N_SCANB];
__device__ int2  g_erec[N_EDGES];         // {src, norm_bits} per CSR slot
__device__ float g_agg[N_NODES * IN_DIM]; // 25.6 MB aggregated features
__device__ int   g_is64;

// ---------------- dtype detection: int64 vs int32 edge_index ----------------
__global__ void detect_k(const int* __restrict__ ei_words, int n_pairs) {
    if (threadIdx.x == 0 && blockIdx.x == 0) {
        int n = n_pairs < 64 ? n_pairs : 64;
        int all_zero = 1;
        #pragma unroll 1
        for (int i = 0; i < n; i++) {
            if (ei_words[2 * i + 1] != 0) { all_zero = 0; break; }
        }
        g_is64 = all_zero;
    }
}

__device__ __forceinline__ void load_edge(const void* __restrict__ ei, int e,
                                          int& src, int& dst) {
    if (g_is64) {
        longlong2 v = ((const longlong2*)ei)[e];
        src = (int)v.x; dst = (int)v.y;
    } else {
        int2 v = ((const int2*)ei)[e];
        src = v.x; dst = v.y;
    }
}

// ---------------- zero counters ----------------
__global__ void zero_k() {
    int i = blockIdx.x * blockDim.x + threadIdx.x;
    if (i < N_NODES) { g_cnt[i] = 0; g_cursor[i] = 0; }
}

// ---------------- degree count (edges only) ----------------
__global__ __launch_bounds__(512) void count_k(const void* __restrict__ ei) {
    int e = blockIdx.x * blockDim.x + threadIdx.x;
    if (e < N_EDGES) {
        int src, dst;
        load_edge(ei, e, src, dst);
        atomicAdd(&g_cnt[dst], 1);
    }
}

// ---------------- scan stage A: per-block sums ----------------
__global__ __launch_bounds__(SCAN_B) void scanA_k() {
    __shared__ int s[SCAN_B];
    int i = blockIdx.x * SCAN_B + threadIdx.x;
    s[threadIdx.x] = (i < N_NODES) ? g_cnt[i] : 0;
    __syncthreads();
    for (int d = SCAN_B / 2; d > 0; d >>= 1) {
        if (threadIdx.x < d) s[threadIdx.x] += s[threadIdx.x + d];
        __syncthreads();
    }
    if (threadIdx.x == 0) g_bsum[blockIdx.x] = s[0];
}

// ---------------- scan stage B: exclusive scan of block sums ----------------
__global__ __launch_bounds__(128) void scanB_k() {
    __shared__ int s[128];
    int t = threadIdx.x;
    s[t] = (t < N_SCANB) ? g_bsum[t] : 0;
    __syncthreads();
    for (int d = 1; d < 128; d <<= 1) {
        int add = (t >= d) ? s[t - d] : 0;
        __syncthreads();
        s[t] += add;
        __syncthreads();
    }
    if (t < N_SCANB) g_bscan[t] = (t == 0) ? 0 : s[t - 1];
}

// ---------------- scan stage C: offsets + dinv ----------------
__global__ __launch_bounds__(SCAN_B) void scanC_k() {
    __shared__ int s[SCAN_B];
    int t = threadIdx.x;
    int i = blockIdx.x * SCAN_B + t;
    int v = (i < N_NODES) ? g_cnt[i] : 0;
    s[t] = v;
    __syncthreads();
    for (int d = 1; d < SCAN_B; d <<= 1) {
        int add = (t >= d) ? s[t - d] : 0;
        __syncthreads();
        s[t] += add;
        __syncthreads();
    }
    if (i < N_NODES) {
        int excl = s[t] - v;                       // exclusive local scan
        g_off[i] = g_bscan[blockIdx.x] + excl;
        g_dinv[i] = rsqrtf((float)(v + 1));        // +1 = self-loop
    }
}

// ---------------- CSR fill: slot = off[dst] + cursor[dst]++ ----------------
__global__ __launch_bounds__(512) void fill_k(const void* __restrict__ ei) {
    int e = blockIdx.x * blockDim.x + threadIdx.x;
    if (e < N_EDGES) {
        int src, dst;
        load_edge(ei, e, src, dst);
        float norm = g_dinv[src] * g_dinv[dst];
        int pos = g_off[dst] + atomicAdd(&g_cursor[dst], 1);
        g_erec[pos] = make_int2(src, __float_as_int(norm));
    }
}

// ---------------- gather: agg[v] = sum_in x[src]*norm (no atomics) ---------
// One warp per node; each lane owns one float4 (32*4 = 128 dims); edges
// iterated 2-wide for MLP. Single plain store per lane at the end.
__global__ __launch_bounds__(256) void gather_k(const float* __restrict__ x) {
    int gt = blockIdx.x * blockDim.x + threadIdx.x;
    int v    = gt >> 5;
    int lane = gt & 31;
    if (v >= N_NODES) return;

    int off = g_off[v];
    int n   = g_cnt[v];

    float4 acc = make_float4(0.f, 0.f, 0.f, 0.f);
    int e = 0;
    for (; e + 2 <= n; e += 2) {
        int2 r0 = g_erec[off + e];
        int2 r1 = g_erec[off + e + 1];
        float4 x0 = ((const float4*)x)[r0.x * 32 + lane];
        float4 x1 = ((const float4*)x)[r1.x * 32 + lane];
        float n0 = __int_as_float(r0.y);
        float n1 = __int_as_float(r1.y);
        acc.x += x0.x * n0; acc.y += x0.y * n0;
        acc.z += x0.z * n0; acc.w += x0.w * n0;
        acc.x += x1.x * n1; acc.y += x1.y * n1;
        acc.z += x1.z * n1; acc.w += x1.w * n1;
    }
    if (e < n) {
        int2 r0 = g_erec[off + e];
        float4 x0 = ((const float4*)x)[r0.x * 32 + lane];
        float n0 = __int_as_float(r0.y);
        acc.x += x0.x * n0; acc.y += x0.y * n0;
        acc.z += x0.z * n0; acc.w += x0.w * n0;
    }
    ((float4*)g_agg)[v * 32 + lane] = acc;
}

// ---------------- tf32 helpers ----------------
__device__ __forceinline__ uint32_t f2tf32(float f) {
    uint32_t r;
    asm("cvt.rna.tf32.f32 %0, %1;" : "=r"(r) : "f"(f));
    return r;
}

// ---------------- GEMM: out = relu((agg + x*dinv^2) @ W^T + b) --------------
// M=50000, N=256, K=128. mma.sync m16n8k8 tf32. BM=128, BN=128, BK=32,
// 256 threads = 8 warps (2 x 4), warp tile 64x32. Self-loop fused in A load.
#define BK 32
#define LDS_PITCH 36   // BK + 4 pad, conflict-free for fragment loads

__global__ __launch_bounds__(256) void gemm_k(const float* __restrict__ x,
                                              const float* __restrict__ W,
                                              const float* __restrict__ bias,
                                              float* __restrict__ out) {
    __shared__ uint32_t As[128 * LDS_PITCH];
    __shared__ uint32_t Bs[128 * LDS_PITCH];

    const int t    = threadIdx.x;
    const int lane = t & 31;
    const int wid  = t >> 5;
    const int wm   = wid & 1;
    const int wn   = wid >> 1;
    const int bm   = blockIdx.x * 128;
    const int bn   = blockIdx.y * 128;

    const int qrow = lane >> 2;
    const int qcol = lane & 3;

    float acc[4][4][4];
    #pragma unroll
    for (int i = 0; i < 4; i++)
        #pragma unroll
        for (int j = 0; j < 4; j++)
            #pragma unroll
            for (int r = 0; r < 4; r++) acc[i][j][r] = 0.f;

    for (int k0 = 0; k0 < IN_DIM; k0 += BK) {
        #pragma unroll
        for (int i = 0; i < 4; i++) {
            int idx = t + i * 256;
            int row = idx >> 3;
            int c4  = (idx & 7) * 4;
            int grow = bm + row;
            float4 av = make_float4(0.f, 0.f, 0.f, 0.f);
            if (grow < N_NODES) {
                av = *(const float4*)&g_agg[grow * IN_DIM + k0 + c4];
                float d = g_dinv[grow];
                float s = d * d;
                float4 xv = *(const float4*)&x[grow * IN_DIM + k0 + c4];
                av.x += xv.x * s; av.y += xv.y * s;
                av.z += xv.z * s; av.w += xv.w * s;
            }
            uint32_t* ap = &As[row * LDS_PITCH + c4];
            ap[0] = f2tf32(av.x); ap[1] = f2tf32(av.y);
            ap[2] = f2tf32(av.z); ap[3] = f2tf32(av.w);

            float4 bv = *(const float4*)&W[(bn + row) * IN_DIM + k0 + c4];
            uint32_t* bp = &Bs[row * LDS_PITCH + c4];
            bp[0] = f2tf32(bv.x); bp[1] = f2tf32(bv.y);
            bp[2] = f2tf32(bv.z); bp[3] = f2tf32(bv.w);
        }
        __syncthreads();

        #pragma unroll
        for (int kk = 0; kk < BK; kk += 8) {
            uint32_t afrag[4][4];
            #pragma unroll
            for (int mt = 0; mt < 4; mt++) {
                int m0 = wm * 64 + mt * 16;
                const uint32_t* base = &As[kk + qcol];
                afrag[mt][0] = base[(m0 + qrow)     * LDS_PITCH];
                afrag[mt][1] = base[(m0 + 8 + qrow) * LDS_PITCH];
                afrag[mt][2] = base[(m0 + qrow)     * LDS_PITCH + 4];
                afrag[mt][3] = base[(m0 + 8 + qrow) * LDS_PITCH + 4];
            }
            uint32_t bfrag[4][2];
            #pragma unroll
            for (int nt = 0; nt < 4; nt++) {
                int n0 = wn * 32 + nt * 8;
                const uint32_t* base = &Bs[(n0 + qrow) * LDS_PITCH + kk + qcol];
                bfrag[nt][0] = base[0];
                bfrag[nt][1] = base[4];
            }
            #pragma unroll
            for (int mt = 0; mt < 4; mt++)
                #pragma unroll
                for (int nt = 0; nt < 4; nt++) {
                    asm volatile(
                        "mma.sync.aligned.m16n8k8.row.col.f32.tf32.tf32.f32 "
                        "{%0,%1,%2,%3}, {%4,%5,%6,%7}, {%8,%9}, {%0,%1,%2,%3};"
                        : "+f"(acc[mt][nt][0]), "+f"(acc[mt][nt][1]),
                          "+f"(acc[mt][nt][2]), "+f"(acc[mt][nt][3])
                        : "r"(afrag[mt][0]), "r"(afrag[mt][1]),
                          "r"(afrag[mt][2]), "r"(afrag[mt][3]),
                          "r"(bfrag[nt][0]), "r"(bfrag[nt][1]));
                }
        }
        __syncthreads();
    }

    #pragma unroll
    for (int mt = 0; mt < 4; mt++) {
        #pragma unroll
        for (int nt = 0; nt < 4; nt++) {
            int row0 = bm + wm * 64 + mt * 16 + qrow;
            int col  = bn + wn * 32 + nt * 8 + qcol * 2;
            float b0 = bias[col], b1 = bias[col + 1];
            if (row0 < N_NODES) {
                float2 r;
                r.x = fmaxf(acc[mt][nt][0] + b0, 0.f);
                r.y = fmaxf(acc[mt][nt][1] + b1, 0.f);
                *(float2*)&out[row0 * OUT_DIM + col] = r;
            }
            int row1 = row0 + 8;
            if (row1 < N_NODES) {
                float2 r;
                r.x = fmaxf(acc[mt][nt][2] + b0, 0.f);
                r.y = fmaxf(acc[mt][nt][3] + b1, 0.f);
                *(float2*)&out[row1 * OUT_DIM + col] = r;
            }
        }
    }
}

// ---------------- launch ----------------
extern "C" void kernel_launch(void* const* d_in, const int* in_sizes, int n_in,
                              void* d_out, int out_size) {
    const float* x  = (const float*)d_in[0];
    const void*  ei = d_in[1];
    const float* W  = (const float*)d_in[2];
    const float* b  = (const float*)d_in[3];
    float* out = (float*)d_out;

    detect_k<<<1, 32>>>((const int*)ei, N_EDGES);
    zero_k<<<(N_NODES + 255) / 256, 256>>>();
    count_k<<<(N_EDGES + 511) / 512, 512>>>(ei);
    scanA_k<<<N_SCANB, SCAN_B>>>();
    scanB_k<<<1, 128>>>();
    scanC_k<<<N_SCANB, SCAN_B>>>();
    fill_k<<<(N_EDGES + 511) / 512, 512>>>(ei);
    gather_k<<<(N_NODES * 32 + 255) / 256, 256>>>(x);
    dim3 grid((N_NODES + 127) / 128, OUT_DIM / 128);
    gemm_k<<<grid, 256>>>(x, W, b, out);
}